// round 1
// baseline (speedup 1.0000x reference)
#include <cuda_runtime.h>
#include <cuda_bf16.h>

// Problem shape (fixed by the reference)
#define BATCH 64
#define TIME  2048
#define FEAT  256
#define MROWS (BATCH * TIME)   // 131072

// Kernel-1 tiling
#define BM 64
#define BN 256
#define BK 16
#define TM 8
#define TN 8
#define K1_THREADS 256   // (ty=tid/32 in 0..7 -> 8-row group; tx=tid%32 -> 8-col group)

#define EPS_V 1e-7f

// Scratch (alloc-free rule: static device globals)
__device__ float g_ait[MROWS];
__device__ float g_a[MROWS];

// ---------------------------------------------------------------------------
// Kernel 1: ait[row] = sum_g u[g] * tanh( (x[row,:] @ W[:,g]) + b[g] )
// Fused GEMM(M=131072,N=256,K=256) + tanh + u-dot. uit never materialized.
// ---------------------------------------------------------------------------
__global__ __launch_bounds__(K1_THREADS)
void k1_gemm_tanh_udot(const float* __restrict__ x,
                       const float* __restrict__ W,
                       const float* __restrict__ bias,
                       const float* __restrict__ u)
{
    __shared__ float xs[BK][BM];        // transposed x tile
    __shared__ float ws[BK][BN];        // W tile

    const int tid  = threadIdx.x;
    const int ty   = tid >> 5;          // 0..7  : row group (== warp id)
    const int tx   = tid & 31;          // 0..31 : col group
    const int rowBase = blockIdx.x * BM;

    float acc[TM][TN];
    #pragma unroll
    for (int i = 0; i < TM; i++)
        #pragma unroll
        for (int j = 0; j < TN; j++) acc[i][j] = 0.0f;

    // load indices for x tile: 256 float4 loads, 1 per thread
    const int xr  = tid >> 2;           // 0..63 row within tile
    const int xkq = tid & 3;            // float4 index along k (k = xkq*4..+3)

    for (int k0 = 0; k0 < FEAT; k0 += BK) {
        // ---- load x tile (64 x 16), store transposed ----
        {
            const float4 v = *reinterpret_cast<const float4*>(
                &x[(size_t)(rowBase + xr) * FEAT + k0 + xkq * 4]);
            xs[xkq * 4 + 0][xr] = v.x;
            xs[xkq * 4 + 1][xr] = v.y;
            xs[xkq * 4 + 2][xr] = v.z;
            xs[xkq * 4 + 3][xr] = v.w;
        }
        // ---- load W tile (16 x 256): 1024 float4 loads, 4 per thread ----
        #pragma unroll
        for (int i = 0; i < 4; i++) {
            const int L    = tid + i * 256;
            const int krow = L >> 6;        // 0..15
            const int cq   = L & 63;        // float4 col index
            *reinterpret_cast<float4*>(&ws[krow][cq * 4]) =
                *reinterpret_cast<const float4*>(&W[(size_t)(k0 + krow) * FEAT + cq * 4]);
        }
        __syncthreads();

        #pragma unroll
        for (int k = 0; k < BK; k++) {
            float a[TM], w[TN];
            #pragma unroll
            for (int i = 0; i < TM; i++) a[i] = xs[k][ty * TM + i];   // warp-broadcast
            #pragma unroll
            for (int j = 0; j < TN; j++) w[j] = ws[k][tx * TN + j];
            #pragma unroll
            for (int i = 0; i < TM; i++)
                #pragma unroll
                for (int j = 0; j < TN; j++)
                    acc[i][j] = fmaf(a[i], w[j], acc[i][j]);
        }
        __syncthreads();
    }

    // ---- epilogue: tanh + dot with u, warp-reduce across 32 col groups ----
    float bv[TN], uv[TN];
    #pragma unroll
    for (int j = 0; j < TN; j++) {
        bv[j] = bias[tx * TN + j];
        uv[j] = u[tx * TN + j];
    }

    #pragma unroll
    for (int i = 0; i < TM; i++) {
        float p = 0.0f;
        #pragma unroll
        for (int j = 0; j < TN; j++)
            p += tanhf(acc[i][j] + bv[j]) * uv[j];
        // all 32 lanes of warp ty hold partials for row ty*8+i
        #pragma unroll
        for (int off = 16; off > 0; off >>= 1)
            p += __shfl_xor_sync(0xffffffffu, p, off);
        if (tx == 0)
            g_ait[rowBase + ty * TM + i] = p;
    }
}

// ---------------------------------------------------------------------------
// Kernel 2: per-batch softmax over T (no max-subtract, matching reference),
//           plus zero-init of d_out for kernel 3's atomics.
// ---------------------------------------------------------------------------
__global__ __launch_bounds__(256)
void k2_softmax(float* __restrict__ out)
{
    const int b   = blockIdx.x;
    const int tid = threadIdx.x;
    __shared__ float red[256];

    float e[TIME / 256];
    float local = 0.0f;
    #pragma unroll
    for (int i = 0; i < TIME / 256; i++) {
        e[i] = __expf(0.0f); // placeholder overwritten below (kept out of fast path)
        float v = g_ait[(size_t)b * TIME + i * 256 + tid];
        e[i] = expf(v);
        local += e[i];
    }
    red[tid] = local;
    __syncthreads();
    #pragma unroll
    for (int s = 128; s > 0; s >>= 1) {
        if (tid < s) red[tid] += red[tid + s];
        __syncthreads();
    }
    const float inv = 1.0f / (red[0] + EPS_V);
    #pragma unroll
    for (int i = 0; i < TIME / 256; i++)
        g_a[(size_t)b * TIME + i * 256 + tid] = e[i] * inv;

    // zero the output (poisoned by harness; kernel 3 atomically accumulates)
    out[b * FEAT + tid] = 0.0f;
}

// ---------------------------------------------------------------------------
// Kernel 3: out[b,f] = sum_t x[b,t,f] * a[b,t]   (time-chunked, atomic accum)
// ---------------------------------------------------------------------------
#define K3_CHUNK 128
__global__ __launch_bounds__(256)
void k3_weighted_sum(const float* __restrict__ x, float* __restrict__ out)
{
    const int b     = blockIdx.y;
    const int chunk = blockIdx.x;
    const int f     = threadIdx.x;

    __shared__ float as[K3_CHUNK];
    if (f < K3_CHUNK)
        as[f] = g_a[(size_t)b * TIME + chunk * K3_CHUNK + f];
    __syncthreads();

    const float* xp = x + ((size_t)b * TIME + (size_t)chunk * K3_CHUNK) * FEAT + f;
    float acc = 0.0f;
    #pragma unroll 8
    for (int t = 0; t < K3_CHUNK; t++)
        acc = fmaf(xp[(size_t)t * FEAT], as[t], acc);

    atomicAdd(&out[b * FEAT + f], acc);
}

// ---------------------------------------------------------------------------
extern "C" void kernel_launch(void* const* d_in, const int* in_sizes, int n_in,
                              void* d_out, int out_size)
{
    const float* x = (const float*)d_in[0];   // (64, 2048, 256)
    const float* W = (const float*)d_in[1];   // (256, 256)
    const float* b = (const float*)d_in[2];   // (256,)
    const float* u = (const float*)d_in[3];   // (256,)
    float* out = (float*)d_out;               // (64, 256)

    k1_gemm_tanh_udot<<<MROWS / BM, K1_THREADS>>>(x, W, b, u);
    k2_softmax<<<BATCH, 256>>>(out);
    dim3 g3(TIME / K3_CHUNK, BATCH);
    k3_weighted_sum<<<g3, 256>>>(x, out);
}

// round 6
// speedup vs baseline: 3.7759x; 3.7759x over previous
#include <cuda_runtime.h>
#include <cuda_fp16.h>
#include <cstdint>

#define BATCH 64
#define TIME  2048
#define FEAT  256
#define MROWS (BATCH * TIME)
#define EPS_V 1e-7f

// ---------------- scratch (static device globals; alloc-free rule) ----------
__device__ float  g_ait[MROWS];
__device__ float  g_a[MROWS];
__device__ __half g_Wh[FEAT * FEAT];   // W transposed: g_Wh[n*FEAT + k] = (half)W[k][n]

__device__ __forceinline__ uint32_t h2_as_u32(__half2 h) {
    return *reinterpret_cast<uint32_t*>(&h);
}

// ---------------- k0: W[k][n] -> g_Wh[n][k] (half) --------------------------
__global__ __launch_bounds__(256)
void k0_wh(const float* __restrict__ W) {
    const int n = blockIdx.x, f = threadIdx.x;
    g_Wh[n * FEAT + f] = __float2half_rn(W[f * FEAT + n]);
}

// ---------------- k1: fp16 mma.sync GEMM + tanh + u-dot ---------------------
#define BM 128
#define BN 256
#define BK 64
#define KT (FEAT / BK)          // 4 outer iterations
#define K1_THREADS 512          // 16 warps: wm = wid%4 (M), wn = wid/4 (N)

#define STRIDE   144            // bytes per row in smem (72 halfs, conflict-free frags)
#define A_BYTES  (BM * STRIDE)  // 18432
#define B_BYTES  (BN * STRIDE)  // 36864
#define STAGE    (A_BYTES + B_BYTES)   // 55296
#define RED_OFF  (2 * STAGE)           // 110592
#define SMEM_SZ  (RED_OFF + 4 * BM * 4)  // + red[4][128] floats = 112640

__device__ __forceinline__ void mma_f16(float* d, const uint32_t* a, const uint32_t* b) {
    asm volatile(
        "mma.sync.aligned.m16n8k16.row.col.f32.f16.f16.f32 "
        "{%0,%1,%2,%3}, {%4,%5,%6,%7}, {%8,%9}, {%0,%1,%2,%3};"
        : "+f"(d[0]), "+f"(d[1]), "+f"(d[2]), "+f"(d[3])
        : "r"(a[0]), "r"(a[1]), "r"(a[2]), "r"(a[3]), "r"(b[0]), "r"(b[1]));
}

__global__ __launch_bounds__(K1_THREADS, 1)
void k1_mma(const float* __restrict__ x, const float* __restrict__ bias,
            const float* __restrict__ u)
{
    extern __shared__ char smem[];
    const int tid = threadIdx.x;
    const int wid = tid >> 5, l = tid & 31;
    const int wm = wid & 3, wn = wid >> 2;
    const int lq = l >> 2, lr = l & 3;          // l/4, l%4
    const size_t rowBase = (size_t)blockIdx.x * BM;

    float acc[2][8][4];
    #pragma unroll
    for (int mt = 0; mt < 2; mt++)
        #pragma unroll
        for (int nt = 0; nt < 8; nt++)
            #pragma unroll
            for (int c = 0; c < 4; c++) acc[mt][nt][c] = 0.0f;

    // ---- prologue ----
    float4 areg[4];
    {   // LDG A(0): 128 rows x 64 floats; 4 float4 per thread
        #pragma unroll
        for (int i = 0; i < 4; i++) {
            const int f4 = tid + i * K1_THREADS;
            const int row = f4 >> 4, q = f4 & 15;
            areg[i] = *reinterpret_cast<const float4*>(&x[(rowBase + row) * FEAT + q * 4]);
        }
        // cp.async B(0): 256 rows x 64 halfs (128B) -> stage 0
        #pragma unroll
        for (int i = 0; i < 4; i++) {
            const int ch = tid + i * K1_THREADS;
            const int n = ch >> 3, q = ch & 7;
            uint32_t dst;
            asm("{ .reg .u64 t; cvta.to.shared.u64 t, %1; cvt.u32.u64 %0, t; }"
                : "=r"(dst) : "l"(smem + A_BYTES + n * STRIDE + q * 16));
            asm volatile("cp.async.cg.shared.global [%0], [%1], 16;"
                         :: "r"(dst), "l"(g_Wh + n * FEAT + q * 8) : "memory");
        }
        asm volatile("cp.async.commit_group;" ::: "memory");
    }

    for (int kt = 0; kt < KT; kt++) {
        char* Ab = smem + (kt & 1) * STAGE;
        char* Bb = Ab + A_BYTES;

        // STS A(kt) from regs (cvt fp32 -> half2)
        #pragma unroll
        for (int i = 0; i < 4; i++) {
            const int f4 = tid + i * K1_THREADS;
            const int row = f4 >> 4, q = f4 & 15;
            uint32_t h0 = h2_as_u32(__floats2half2_rn(areg[i].x, areg[i].y));
            uint32_t h1 = h2_as_u32(__floats2half2_rn(areg[i].z, areg[i].w));
            *reinterpret_cast<uint2*>(Ab + row * STRIDE + q * 8) = make_uint2(h0, h1);
        }
        asm volatile("cp.async.wait_group 0;" ::: "memory");
        __syncthreads();

        if (kt < KT - 1) {
            const int k0 = (kt + 1) * BK;
            char* Bn = smem + ((kt + 1) & 1) * STAGE + A_BYTES;
            #pragma unroll
            for (int i = 0; i < 4; i++) {
                const int ch = tid + i * K1_THREADS;
                const int n = ch >> 3, q = ch & 7;
                uint32_t dst;
                asm("{ .reg .u64 t; cvta.to.shared.u64 t, %1; cvt.u32.u64 %0, t; }"
                    : "=r"(dst) : "l"(Bn + n * STRIDE + q * 16));
                asm volatile("cp.async.cg.shared.global [%0], [%1], 16;"
                             :: "r"(dst), "l"(g_Wh + n * FEAT + k0 + q * 8) : "memory");
            }
            asm volatile("cp.async.commit_group;" ::: "memory");
            #pragma unroll
            for (int i = 0; i < 4; i++) {
                const int f4 = tid + i * K1_THREADS;
                const int row = f4 >> 4, q = f4 & 15;
                areg[i] = *reinterpret_cast<const float4*>(&x[(rowBase + row) * FEAT + k0 + q * 4]);
            }
        }

        // ---- compute: 4 k16-steps ----
        const char* Aw = Ab + (wm * 32 + lq) * STRIDE + lr * 4;
        const char* Bw = Bb + (wn * 64 + lq) * STRIDE + lr * 4;
        #pragma unroll
        for (int ks = 0; ks < 4; ks++) {
            uint32_t af[2][4];
            #pragma unroll
            for (int mt = 0; mt < 2; mt++) {
                const char* p = Aw + mt * 16 * STRIDE + ks * 32;
                af[mt][0] = *reinterpret_cast<const uint32_t*>(p);
                af[mt][1] = *reinterpret_cast<const uint32_t*>(p + 8 * STRIDE);
                af[mt][2] = *reinterpret_cast<const uint32_t*>(p + 16);
                af[mt][3] = *reinterpret_cast<const uint32_t*>(p + 8 * STRIDE + 16);
            }
            #pragma unroll
            for (int nt = 0; nt < 8; nt++) {
                const char* p = Bw + nt * 8 * STRIDE + ks * 32;
                uint32_t bf[2];
                bf[0] = *reinterpret_cast<const uint32_t*>(p);
                bf[1] = *reinterpret_cast<const uint32_t*>(p + 16);
                mma_f16(acc[0][nt], af[0], bf);
                mma_f16(acc[1][nt], af[1], bf);
            }
        }
        __syncthreads();
    }

    // ---- epilogue: tanh + u-dot ----
    float bv[16], uv[16];
    #pragma unroll
    for (int nt = 0; nt < 8; nt++)
        #pragma unroll
        for (int d = 0; d < 2; d++) {
            const int col = wn * 64 + nt * 8 + lr * 2 + d;
            bv[nt * 2 + d] = bias[col];
            uv[nt * 2 + d] = u[col];
        }

    float* red = reinterpret_cast<float*>(smem + RED_OFF);
    #pragma unroll
    for (int mt = 0; mt < 2; mt++) {
        float p0 = 0.0f, p1 = 0.0f;
        #pragma unroll
        for (int nt = 0; nt < 8; nt++)
            #pragma unroll
            for (int d = 0; d < 2; d++) {
                {
                    const float v = acc[mt][nt][d] + bv[nt * 2 + d];
                    const float t = 1.0f - __fdividef(2.0f, __expf(v + v) + 1.0f);
                    p0 = fmaf(t, uv[nt * 2 + d], p0);
                }
                {
                    const float v = acc[mt][nt][2 + d] + bv[nt * 2 + d];
                    const float t = 1.0f - __fdividef(2.0f, __expf(v + v) + 1.0f);
                    p1 = fmaf(t, uv[nt * 2 + d], p1);
                }
            }
        #pragma unroll
        for (int off = 2; off > 0; off >>= 1) {
            p0 += __shfl_xor_sync(0xffffffffu, p0, off);
            p1 += __shfl_xor_sync(0xffffffffu, p1, off);
        }
        if (lr == 0) {
            red[wn * BM + wm * 32 + mt * 16 + lq]     = p0;
            red[wn * BM + wm * 32 + mt * 16 + lq + 8] = p1;
        }
    }
    __syncthreads();
    if (tid < BM) {
        const float s = red[tid] + red[BM + tid] + red[2 * BM + tid] + red[3 * BM + tid];
        g_ait[rowBase + tid] = s;
    }
}

// ---------------- k2: per-batch softmax + zero out ---------------------------
__global__ __launch_bounds__(256)
void k2_softmax(float* __restrict__ out) {
    const int b = blockIdx.x, tid = threadIdx.x;
    __shared__ float red[256];
    float e[TIME / 256];
    float local = 0.0f;
    #pragma unroll
    for (int i = 0; i < TIME / 256; i++) {
        e[i] = expf(g_ait[(size_t)b * TIME + i * 256 + tid]);
        local += e[i];
    }
    red[tid] = local;
    __syncthreads();
    #pragma unroll
    for (int s = 128; s > 0; s >>= 1) {
        if (tid < s) red[tid] += red[tid + s];
        __syncthreads();
    }
    const float inv = 1.0f / (red[0] + EPS_V);
    #pragma unroll
    for (int i = 0; i < TIME / 256; i++)
        g_a[(size_t)b * TIME + i * 256 + tid] = e[i] * inv;
    out[b * FEAT + tid] = 0.0f;
}

// ---------------- k3: out[b,f] = sum_t x[b,t,f] * a[b,t] --------------------
#define K3_CHUNK 128
__global__ __launch_bounds__(256)
void k3_weighted_sum(const float* __restrict__ x, float* __restrict__ out) {
    const int b = blockIdx.y, chunk = blockIdx.x, f = threadIdx.x;
    __shared__ float as[K3_CHUNK];
    if (f < K3_CHUNK)
        as[f] = g_a[(size_t)b * TIME + chunk * K3_CHUNK + f];
    __syncthreads();
    const float* xp = x + ((size_t)b * TIME + (size_t)chunk * K3_CHUNK) * FEAT + f;
    float acc = 0.0f;
    #pragma unroll 8
    for (int t = 0; t < K3_CHUNK; t++)
        acc = fmaf(xp[(size_t)t * FEAT], as[t], acc);
    atomicAdd(&out[b * FEAT + f], acc);
}

// ---------------------------------------------------------------------------
extern "C" void kernel_launch(void* const* d_in, const int* in_sizes, int n_in,
                              void* d_out, int out_size) {
    const float* x = (const float*)d_in[0];
    const float* W = (const float*)d_in[1];
    const float* b = (const float*)d_in[2];
    const float* u = (const float*)d_in[3];
    float* out = (float*)d_out;

    cudaFuncSetAttribute(k1_mma, cudaFuncAttributeMaxDynamicSharedMemorySize, SMEM_SZ);

    k0_wh<<<FEAT, FEAT>>>(W);
    k1_mma<<<MROWS / BM, K1_THREADS, SMEM_SZ>>>(x, b, u);
    k2_softmax<<<BATCH, 256>>>(out);
    dim3 g3(TIME / K3_CHUNK, BATCH);
    k3_weighted_sum<<<g3, 256>>>(x, out);
}

// round 7
// speedup vs baseline: 4.1867x; 1.1088x over previous
#include <cuda_runtime.h>
#include <cuda_fp16.h>
#include <cstdint>

#define BATCH 64
#define TIME  2048
#define FEAT  256
#define MROWS (BATCH * TIME)
#define EPS_V 1e-7f

// ---------------- scratch (static device globals; alloc-free rule) ----------
__device__ __half g_Wh[FEAT * FEAT];       // W transposed: g_Wh[n*FEAT+k] = (half)W[k][n]
__device__ float  g_part[(MROWS / 128) * FEAT];  // per-CTA numerator partials (1024 x 256)
__device__ float  g_denp[MROWS / 128];           // per-CTA denominator partials

__device__ __forceinline__ uint32_t h2_as_u32(__half2 h) {
    return *reinterpret_cast<uint32_t*>(&h);
}

// ---------------- k0: W[k][n] -> g_Wh[n][k] (half) --------------------------
__global__ __launch_bounds__(256)
void k0_wh(const float* __restrict__ W) {
    const int n = blockIdx.x, f = threadIdx.x;
    g_Wh[n * FEAT + f] = __float2half_rn(W[f * FEAT + n]);
}

// ---------------- k1: fp16 mma GEMM + tanh + u-dot + exp + weighted-x -------
#define BM 128
#define BN 256
#define BK 64
#define KT (FEAT / BK)          // 4 outer iterations
#define K1_THREADS 512          // 16 warps: wm = wid%4 (M), wn = wid/4 (N)

#define STRIDE   144            // bytes per smem row (72 halfs, conflict-free frags)
#define A_BYTES  (BM * STRIDE)  // 18432
#define B_BYTES  (BN * STRIDE)  // 36864
#define STAGE    (A_BYTES + B_BYTES)   // 55296
#define RED_OFF  (2 * STAGE)           // 110592 : red[512] floats (2048B)
#define ES_OFF   (RED_OFF + 2048)      // e_s[128] floats (512B)
#define WP_OFF   (ES_OFF + 512)        // wp[4] floats
#define SMEM_SZ  (WP_OFF + 32)

__device__ __forceinline__ void mma_f16(float* d, const uint32_t* a, const uint32_t* b) {
    asm volatile(
        "mma.sync.aligned.m16n8k16.row.col.f32.f16.f16.f32 "
        "{%0,%1,%2,%3}, {%4,%5,%6,%7}, {%8,%9}, {%0,%1,%2,%3};"
        : "+f"(d[0]), "+f"(d[1]), "+f"(d[2]), "+f"(d[3])
        : "r"(a[0]), "r"(a[1]), "r"(a[2]), "r"(a[3]), "r"(b[0]), "r"(b[1]));
}

__global__ __launch_bounds__(K1_THREADS, 1)
void k1_mma(const float* __restrict__ x, const float* __restrict__ bias,
            const float* __restrict__ u)
{
    extern __shared__ char smem[];
    const int tid = threadIdx.x;
    const int wid = tid >> 5, l = tid & 31;
    const int wm = wid & 3, wn = wid >> 2;
    const int lq = l >> 2, lr = l & 3;
    const size_t rowBase = (size_t)blockIdx.x * BM;

    float acc[2][8][4];
    #pragma unroll
    for (int mt = 0; mt < 2; mt++)
        #pragma unroll
        for (int nt = 0; nt < 8; nt++)
            #pragma unroll
            for (int c = 0; c < 4; c++) acc[mt][nt][c] = 0.0f;

    // ---- prologue ----
    float4 areg[4];
    {
        #pragma unroll
        for (int i = 0; i < 4; i++) {
            const int f4 = tid + i * K1_THREADS;
            const int row = f4 >> 4, q = f4 & 15;
            areg[i] = *reinterpret_cast<const float4*>(&x[(rowBase + row) * FEAT + q * 4]);
        }
        #pragma unroll
        for (int i = 0; i < 4; i++) {
            const int ch = tid + i * K1_THREADS;
            const int n = ch >> 3, q = ch & 7;
            uint32_t dst;
            asm("{ .reg .u64 t; cvta.to.shared.u64 t, %1; cvt.u32.u64 %0, t; }"
                : "=r"(dst) : "l"(smem + A_BYTES + n * STRIDE + q * 16));
            asm volatile("cp.async.cg.shared.global [%0], [%1], 16;"
                         :: "r"(dst), "l"(g_Wh + n * FEAT + q * 8) : "memory");
        }
        asm volatile("cp.async.commit_group;" ::: "memory");
    }

    for (int kt = 0; kt < KT; kt++) {
        char* Ab = smem + (kt & 1) * STAGE;
        char* Bb = Ab + A_BYTES;

        #pragma unroll
        for (int i = 0; i < 4; i++) {
            const int f4 = tid + i * K1_THREADS;
            const int row = f4 >> 4, q = f4 & 15;
            uint32_t h0 = h2_as_u32(__floats2half2_rn(areg[i].x, areg[i].y));
            uint32_t h1 = h2_as_u32(__floats2half2_rn(areg[i].z, areg[i].w));
            *reinterpret_cast<uint2*>(Ab + row * STRIDE + q * 8) = make_uint2(h0, h1);
        }
        asm volatile("cp.async.wait_group 0;" ::: "memory");
        __syncthreads();

        if (kt < KT - 1) {
            const int k0 = (kt + 1) * BK;
            char* Bn = smem + ((kt + 1) & 1) * STAGE + A_BYTES;
            #pragma unroll
            for (int i = 0; i < 4; i++) {
                const int ch = tid + i * K1_THREADS;
                const int n = ch >> 3, q = ch & 7;
                uint32_t dst;
                asm("{ .reg .u64 t; cvta.to.shared.u64 t, %1; cvt.u32.u64 %0, t; }"
                    : "=r"(dst) : "l"(Bn + n * STRIDE + q * 16));
                asm volatile("cp.async.cg.shared.global [%0], [%1], 16;"
                             :: "r"(dst), "l"(g_Wh + n * FEAT + k0 + q * 8) : "memory");
            }
            asm volatile("cp.async.commit_group;" ::: "memory");
            #pragma unroll
            for (int i = 0; i < 4; i++) {
                const int f4 = tid + i * K1_THREADS;
                const int row = f4 >> 4, q = f4 & 15;
                areg[i] = *reinterpret_cast<const float4*>(&x[(rowBase + row) * FEAT + k0 + q * 4]);
            }
        }

        // ---- compute: 4 k16-steps ----
        const char* Aw = Ab + (wm * 32 + lq) * STRIDE + lr * 4;
        const char* Bw = Bb + (wn * 64 + lq) * STRIDE + lr * 4;
        #pragma unroll
        for (int ks = 0; ks < 4; ks++) {
            uint32_t af[2][4];
            #pragma unroll
            for (int mt = 0; mt < 2; mt++) {
                const char* p = Aw + mt * 16 * STRIDE + ks * 32;
                af[mt][0] = *reinterpret_cast<const uint32_t*>(p);
                af[mt][1] = *reinterpret_cast<const uint32_t*>(p + 8 * STRIDE);
                af[mt][2] = *reinterpret_cast<const uint32_t*>(p + 16);
                af[mt][3] = *reinterpret_cast<const uint32_t*>(p + 8 * STRIDE + 16);
            }
            #pragma unroll
            for (int nt = 0; nt < 8; nt++) {
                const char* p = Bw + nt * 8 * STRIDE + ks * 32;
                uint32_t bf[2];
                bf[0] = *reinterpret_cast<const uint32_t*>(p);
                bf[1] = *reinterpret_cast<const uint32_t*>(p + 16);
                mma_f16(acc[0][nt], af[0], bf);
                mma_f16(acc[1][nt], af[1], bf);
            }
        }
        __syncthreads();
    }

    // ---- epilogue stage 1: tanh + u-dot per accum, reduce to per-row ait ----
    float bv[16], uv[16];
    #pragma unroll
    for (int nt = 0; nt < 8; nt++)
        #pragma unroll
        for (int d = 0; d < 2; d++) {
            const int col = wn * 64 + nt * 8 + lr * 2 + d;
            bv[nt * 2 + d] = bias[col];
            uv[nt * 2 + d] = u[col];
        }

    float* red = reinterpret_cast<float*>(smem + RED_OFF);   // 512 floats
    float* e_s = reinterpret_cast<float*>(smem + ES_OFF);    // 128 floats
    float* wp  = reinterpret_cast<float*>(smem + WP_OFF);    // 4 floats
    #pragma unroll
    for (int mt = 0; mt < 2; mt++) {
        float p0 = 0.0f, p1 = 0.0f;
        #pragma unroll
        for (int nt = 0; nt < 8; nt++)
            #pragma unroll
            for (int d = 0; d < 2; d++) {
                {
                    const float v = acc[mt][nt][d] + bv[nt * 2 + d];
                    const float t = 1.0f - __fdividef(2.0f, __expf(v + v) + 1.0f);
                    p0 = fmaf(t, uv[nt * 2 + d], p0);
                }
                {
                    const float v = acc[mt][nt][2 + d] + bv[nt * 2 + d];
                    const float t = 1.0f - __fdividef(2.0f, __expf(v + v) + 1.0f);
                    p1 = fmaf(t, uv[nt * 2 + d], p1);
                }
            }
        #pragma unroll
        for (int off = 2; off > 0; off >>= 1) {
            p0 += __shfl_xor_sync(0xffffffffu, p0, off);
            p1 += __shfl_xor_sync(0xffffffffu, p1, off);
        }
        if (lr == 0) {
            red[wn * BM + wm * 32 + mt * 16 + lq]     = p0;
            red[wn * BM + wm * 32 + mt * 16 + lq + 8] = p1;
        }
    }
    __syncthreads();

    // ---- epilogue stage 2: e = exp(ait); per-CTA denominator partial -------
    if (tid < BM) {
        const float s = red[tid] + red[BM + tid] + red[2 * BM + tid] + red[3 * BM + tid];
        const float e = expf(s);
        e_s[tid] = e;
        float w = e;
        #pragma unroll
        for (int off = 16; off > 0; off >>= 1)
            w += __shfl_xor_sync(0xffffffffu, w, off);
        if (l == 0) wp[wid] = w;
    }
    __syncthreads();
    if (tid == 0)
        g_denp[blockIdx.x] = wp[0] + wp[1] + wp[2] + wp[3];

    // ---- epilogue stage 3: numerator partial = sum_rows x[row,col]*e[row] --
    // x tile just streamed by this CTA -> L2-resident. Coalesced re-read.
    {
        const int col = tid & 255;
        const int rowgrp = tid >> 8;              // 0 or 1 -> rows 0..63 / 64..127
        const float* xp = x + (rowBase + (size_t)rowgrp * 64) * FEAT + col;
        const float* ep = e_s + rowgrp * 64;
        float a0 = 0.0f, a1 = 0.0f;
        #pragma unroll 8
        for (int i = 0; i < 64; i += 2) {
            a0 = fmaf(xp[(size_t)i * FEAT], ep[i], a0);
            a1 = fmaf(xp[(size_t)(i + 1) * FEAT], ep[i + 1], a1);
        }
        red[tid] = a0 + a1;     // red reused (after sync above)
    }
    __syncthreads();
    if (tid < FEAT)
        g_part[blockIdx.x * FEAT + tid] = red[tid] + red[FEAT + tid];
}

// ---------------- k_final: out[b,f] = num/(den+eps) -------------------------
#define CTAS_PER_B (TIME / BM)   // 16
__global__ __launch_bounds__(256)
void k_final(float* __restrict__ out) {
    const int b = blockIdx.x, tid = threadIdx.x;
    float den = 0.0f;
    #pragma unroll
    for (int i = 0; i < CTAS_PER_B; i++)
        den += g_denp[b * CTAS_PER_B + i];
    float num = 0.0f;
    #pragma unroll
    for (int i = 0; i < CTAS_PER_B; i++)
        num += g_part[(b * CTAS_PER_B + i) * FEAT + tid];
    out[b * FEAT + tid] = num / (den + EPS_V);
}

// ---------------------------------------------------------------------------
extern "C" void kernel_launch(void* const* d_in, const int* in_sizes, int n_in,
                              void* d_out, int out_size) {
    const float* x = (const float*)d_in[0];
    const float* W = (const float*)d_in[1];
    const float* b = (const float*)d_in[2];
    const float* u = (const float*)d_in[3];
    float* out = (float*)d_out;

    cudaFuncSetAttribute(k1_mma, cudaFuncAttributeMaxDynamicSharedMemorySize, SMEM_SZ);

    k0_wh<<<FEAT, FEAT>>>(W);
    k1_mma<<<MROWS / BM, K1_THREADS, SMEM_SZ>>>(x, b, u);
    k_final<<<BATCH, FEAT>>>(out);
}